// round 3
// baseline (speedup 1.0000x reference)
#include <cuda_runtime.h>

// RadarSparseProcessor: out[v,o] = (sum_p sum_c x[v,p,c] * W[o,c]) / max(n_v, 1)
// V = 1048576, P = 4, C_IN = 4, C_OUT = 32. vnp is int32.
//
// R3: 8 lanes per voxel -> fully coalesced loads (float2/lane) and stores
// (float4/lane), point-reduction via 3 shfl.xor stages. Target: DRAM-bound.

#define THREADS 256

__global__ __launch_bounds__(THREADS)
void radar_sparse_kernel(const float2* __restrict__ in2,  // [V*8] float2 (= [V,4,4] f32)
                         const float*  __restrict__ W,    // [32,4]
                         const int*    __restrict__ vnp,  // [V] int32
                         float4* __restrict__ out4,       // [V*8] float4 (= [V,32])
                         int total)                       // V*8
{
    __shared__ float sW[128];
    if (threadIdx.x < 32) {
        ((float4*)sW)[threadIdx.x] = ((const float4*)W)[threadIdx.x];
    }
    __syncthreads();

    int gidx = blockIdx.x * blockDim.x + threadIdx.x;
    if (gidx >= total) return;

    int t = gidx & 7;        // lane-in-voxel 0..7
    int v = gidx >> 3;       // voxel id

    // Coalesced load: this thread's 2 floats of the voxel's 16.
    float2 d = in2[gidx];
    float a = d.x, b = d.y;
    // Thread t holds floats (2t, 2t+1) of [P=4,C=4] row-major:
    // bit0 of t selects channel pair (c0c1 vs c2c3), bits1-2 select point.
    // Sum over points: butterfly over xor 2 and xor 4.
    a += __shfl_xor_sync(0xFFFFFFFFu, a, 2);
    b += __shfl_xor_sync(0xFFFFFFFFu, b, 2);
    a += __shfl_xor_sync(0xFFFFFFFFu, a, 4);
    b += __shfl_xor_sync(0xFFFFFFFFu, b, 4);
    // Now even t: (a,b) = (s0,s1); odd t: (a,b) = (s2,s3).
    float ra = __shfl_xor_sync(0xFFFFFFFFu, a, 1);
    float rb = __shfl_xor_sync(0xFFFFFFFFu, b, 1);
    float s0, s1, s2, s3;
    if (t & 1) { s0 = ra; s1 = rb; s2 = a;  s3 = b;  }
    else       { s0 = a;  s1 = b;  s2 = ra; s3 = rb; }

    int n = vnp[v];                       // 8-way broadcast, 1 sector per warp
    float inv = 1.0f / (float)(n > 1 ? n : 1);

    // Lane t computes output channels 4t .. 4t+3.
    const float4* wrow = (const float4*)&sW[t * 16];
    float4 w0 = wrow[0], w1 = wrow[1], w2 = wrow[2], w3 = wrow[3];

    float4 o;
    o.x = fmaf(w0.x, s0, fmaf(w0.y, s1, fmaf(w0.z, s2, w0.w * s3))) * inv;
    o.y = fmaf(w1.x, s0, fmaf(w1.y, s1, fmaf(w1.z, s2, w1.w * s3))) * inv;
    o.z = fmaf(w2.x, s0, fmaf(w2.y, s1, fmaf(w2.z, s2, w2.w * s3))) * inv;
    o.w = fmaf(w3.x, s0, fmaf(w3.y, s1, fmaf(w3.z, s2, w3.w * s3))) * inv;

    out4[gidx] = o;   // perfectly coalesced: warp writes one contiguous 512 B span
}

extern "C" void kernel_launch(void* const* d_in, const int* in_sizes, int n_in,
                              void* d_out, int out_size)
{
    const float2* in2 = (const float2*)d_in[0];   // voxel_features [V,4,4] f32
    const float*  W   = (const float*)d_in[1];    // W [32,4] f32
    const int*    vnp = (const int*)d_in[2];      // voxel_num_points [V] i32
    float4*       out = (float4*)d_out;           // [V,32] f32

    int V = in_sizes[2];
    int total = V * 8;                            // 8 lanes per voxel
    int blocks = (total + THREADS - 1) / THREADS;
    radar_sparse_kernel<<<blocks, THREADS>>>(in2, W, vnp, out, total);
}

// round 4
// speedup vs baseline: 2.0748x; 2.0748x over previous
#include <cuda_runtime.h>

// RadarSparseProcessor: out[v,o] = (sum_p sum_c x[v,p,c] * W[o,c]) / max(n_v, 1)
// V = 1048576, P = 4, C_IN = 4, C_OUT = 32. vnp is int32.
//
// R4: smem-staged transpose. Coalesced LDG in, conflict-free smem transpose
// (stride-5-float4 padding), per-thread voxel reduce with inv folded in,
// then a warp-cooperative store loop with perfectly contiguous STG.128.

#define THREADS 256
#define VPB 256                // voxels per block (== THREADS)

__global__ __launch_bounds__(THREADS)
void radar_sparse_kernel(const float4* __restrict__ in4,  // [V*4] float4 (= [V,4,4])
                         const float4* __restrict__ W4,   // [32] float4 (= [32,4])
                         const int*    __restrict__ vnp,  // [V] int32
                         float4* __restrict__ out4,       // [V*8] float4 (= [V,32])
                         int V)
{
    __shared__ float4 sIn[VPB * 5];   // padded: voxel v at sIn[v*5 + c], c=0..3
    __shared__ float4 sS[VPB];        // s-vector * inv per voxel
    __shared__ float4 sW[32];         // W rows

    const int tid = threadIdx.x;
    const int vblock = blockIdx.x * VPB;

    if (tid < 32) sW[tid] = W4[tid];

    // ---- Stage input, coalesced: block covers VPB*4 float4s ----
    const int base4 = vblock * 4;
    #pragma unroll
    for (int k = 0; k < 4; k++) {
        int local = k * THREADS + tid;          // 0 .. VPB*4-1
        int j = base4 + local;
        if (j < V * 4) {
            float4 val = in4[j];
            sIn[(local >> 2) * 5 + (local & 3)] = val;
        }
    }
    __syncthreads();

    // ---- Per-thread: reduce points, fold in 1/max(n,1) ----
    {
        int v = vblock + tid;
        if (v < V) {
            float4 p0 = sIn[tid * 5 + 0];
            float4 p1 = sIn[tid * 5 + 1];
            float4 p2 = sIn[tid * 5 + 2];
            float4 p3 = sIn[tid * 5 + 3];
            int n = vnp[v];                          // coalesced LDG.32
            float inv = 1.0f / (float)(n > 1 ? n : 1);
            float4 s;
            s.x = ((p0.x + p1.x) + (p2.x + p3.x)) * inv;
            s.y = ((p0.y + p1.y) + (p2.y + p3.y)) * inv;
            s.z = ((p0.z + p1.z) + (p2.z + p3.z)) * inv;
            s.w = ((p0.w + p1.w) + (p2.w + p3.w)) * inv;
            sS[tid] = s;
        }
    }
    __syncthreads();

    // ---- Warp-cooperative coalesced store ----
    // Warp w owns local voxels [w*32, w*32+32). Lane l: sub = l>>3 picks the
    // voxel within a 4-voxel group, ch8 = l&7 picks the channel quad.
    const int wid  = tid >> 5;
    const int lane = tid & 31;
    const int sub  = lane >> 3;
    const int ch8  = lane & 7;

    // Weight rows for channels 4*ch8 .. 4*ch8+3 (one-time, broadcast LDS)
    float4 w0 = sW[ch8 * 4 + 0];
    float4 w1 = sW[ch8 * 4 + 1];
    float4 w2 = sW[ch8 * 4 + 2];
    float4 w3 = sW[ch8 * 4 + 3];

    const int warpVoxLocal = wid * 32;
    float4* outBase = out4 + (size_t)(vblock + warpVoxLocal) * 8;

    #pragma unroll
    for (int i = 0; i < 8; i++) {
        int vl = warpVoxLocal + i * 4 + sub;     // local voxel
        if (vblock + vl < V) {
            float4 s = sS[vl];                   // 8-way broadcast, conflict-free
            float4 o;
            o.x = fmaf(w0.x, s.x, fmaf(w0.y, s.y, fmaf(w0.z, s.z, w0.w * s.w)));
            o.y = fmaf(w1.x, s.x, fmaf(w1.y, s.y, fmaf(w1.z, s.z, w1.w * s.w)));
            o.z = fmaf(w2.x, s.x, fmaf(w2.y, s.y, fmaf(w2.z, s.z, w2.w * s.w)));
            o.w = fmaf(w3.x, s.x, fmaf(w3.y, s.y, fmaf(w3.z, s.z, w3.w * s.w)));
            outBase[i * 32 + lane] = o;          // contiguous 512 B per warp
        }
    }
}

extern "C" void kernel_launch(void* const* d_in, const int* in_sizes, int n_in,
                              void* d_out, int out_size)
{
    const float4* in4 = (const float4*)d_in[0];   // voxel_features [V,4,4] f32
    const float4* W4  = (const float4*)d_in[1];   // W [32,4] f32
    const int*    vnp = (const int*)d_in[2];      // voxel_num_points [V] i32
    float4*       out = (float4*)d_out;           // [V,32] f32

    int V = in_sizes[2];
    int blocks = (V + VPB - 1) / VPB;
    radar_sparse_kernel<<<blocks, THREADS>>>(in4, W4, vnp, out, V);
}

// round 5
// speedup vs baseline: 2.0975x; 1.0109x over previous
#include <cuda_runtime.h>

// RadarSparseProcessor: out[v,o] = (sum_p sum_c x[v,p,c] * W[o,c]) / max(n_v, 1)
// V = 1048576, P = 4, C_IN = 4, C_OUT = 32. vnp is int32.
//
// R5: warp-autonomous, zero smem, zero block barriers.
// Coalesced LDG -> register butterfly (shfl.xor) point-reduce -> shfl.idx
// redistribute -> contiguous STG.128. L1 wavefronts ~51/warp (floor=48).

#define THREADS 256

__global__ __launch_bounds__(THREADS)
void radar_sparse_kernel(const float4* __restrict__ in4,  // [V*4] float4 (= [V,4,4])
                         const float4* __restrict__ W4,   // [32] float4 (= [32,4])
                         const int*    __restrict__ vnp,  // [V] int32
                         float4* __restrict__ out4,       // [V*8] float4 (= [V,32])
                         int V)
{
    const unsigned FULL = 0xFFFFFFFFu;
    const int lane  = threadIdx.x & 31;
    const int gwarp = (blockIdx.x * blockDim.x + threadIdx.x) >> 5;
    const int vbase = gwarp * 32;                 // first voxel of this warp
    if (vbase >= V) return;

    // Weight rows for this lane's channel quad q = lane&7 (channels 4q..4q+3).
    const int q = lane & 7;
    const float4 w0 = W4[q * 4 + 0];
    const float4 w1 = W4[q * 4 + 1];
    const float4 w2 = W4[q * 4 + 2];
    const float4 w3 = W4[q * 4 + 3];

    if (vbase + 32 <= V) {
        // ---------- fast path: full warp of 32 voxels ----------
        // inv for voxel vbase+lane (coalesced)
        int n = vnp[vbase + lane];
        float invl = 1.0f / (float)(n > 1 ? n : 1);

        // Load 128 contiguous float4 (2048 B): iter k, lane l -> idx k*32+l.
        // That float4 is point (l&3) of voxel 8k + (l>>2).
        const float4* inBase = in4 + (size_t)vbase * 4;
        float4 s[4];
        #pragma unroll
        for (int k = 0; k < 4; k++) {
            float4 d = inBase[k * 32 + lane];
            // butterfly sum over the point dimension (4-lane groups)
            d.x += __shfl_xor_sync(FULL, d.x, 1);
            d.y += __shfl_xor_sync(FULL, d.y, 1);
            d.z += __shfl_xor_sync(FULL, d.z, 1);
            d.w += __shfl_xor_sync(FULL, d.w, 1);
            d.x += __shfl_xor_sync(FULL, d.x, 2);
            d.y += __shfl_xor_sync(FULL, d.y, 2);
            d.z += __shfl_xor_sync(FULL, d.z, 2);
            d.w += __shfl_xor_sync(FULL, d.w, 2);
            // fold in 1/max(n,1) of voxel 8k + (l>>2)
            float ik = __shfl_sync(FULL, invl, 8 * k + (lane >> 2));
            d.x *= ik; d.y *= ik; d.z *= ik; d.w *= ik;
            s[k] = d;   // all 4 lanes of the group hold s of voxel 8k+(l>>2)
        }

        // Store: iter i covers voxels 4i..4i+3 (32 contiguous float4).
        // Lane l writes voxel 4i+(l>>3), quad q. s source lane: 16(i&1)+4(l>>3).
        float4* outBase = out4 + (size_t)vbase * 8;
        #pragma unroll
        for (int i = 0; i < 8; i++) {
            const int k = i >> 1;
            const int src = 16 * (i & 1) + 4 * (lane >> 3);
            float4 sv;
            sv.x = __shfl_sync(FULL, s[k].x, src);
            sv.y = __shfl_sync(FULL, s[k].y, src);
            sv.z = __shfl_sync(FULL, s[k].z, src);
            sv.w = __shfl_sync(FULL, s[k].w, src);
            float4 o;
            o.x = fmaf(w0.x, sv.x, fmaf(w0.y, sv.y, fmaf(w0.z, sv.z, w0.w * sv.w)));
            o.y = fmaf(w1.x, sv.x, fmaf(w1.y, sv.y, fmaf(w1.z, sv.z, w1.w * sv.w)));
            o.z = fmaf(w2.x, sv.x, fmaf(w2.y, sv.y, fmaf(w2.z, sv.z, w2.w * sv.w)));
            o.w = fmaf(w3.x, sv.x, fmaf(w3.y, sv.y, fmaf(w3.z, sv.z, w3.w * sv.w)));
            outBase[i * 32 + lane] = o;          // contiguous 512 B per warp
        }
    } else {
        // ---------- tail path: per-lane scalar (rare / absent for V=1M) ----------
        int v = vbase + lane;
        if (v < V) {
            const float4* vrow = in4 + (size_t)v * 4;
            float4 p0 = vrow[0], p1 = vrow[1], p2 = vrow[2], p3 = vrow[3];
            int n = vnp[v];
            float inv = 1.0f / (float)(n > 1 ? n : 1);
            float sx = ((p0.x + p1.x) + (p2.x + p3.x)) * inv;
            float sy = ((p0.y + p1.y) + (p2.y + p3.y)) * inv;
            float sz = ((p0.z + p1.z) + (p2.z + p3.z)) * inv;
            float sw = ((p0.w + p1.w) + (p2.w + p3.w)) * inv;
            float4* orow = out4 + (size_t)v * 8;
            #pragma unroll
            for (int kk = 0; kk < 8; kk++) {
                float4 a = W4[kk * 4 + 0], b = W4[kk * 4 + 1];
                float4 c = W4[kk * 4 + 2], d = W4[kk * 4 + 3];
                float4 o;
                o.x = fmaf(a.x, sx, fmaf(a.y, sy, fmaf(a.z, sz, a.w * sw)));
                o.y = fmaf(b.x, sx, fmaf(b.y, sy, fmaf(b.z, sz, b.w * sw)));
                o.z = fmaf(c.x, sx, fmaf(c.y, sy, fmaf(c.z, sz, c.w * sw)));
                o.w = fmaf(d.x, sx, fmaf(d.y, sy, fmaf(d.z, sz, d.w * sw)));
                orow[kk] = o;
            }
        }
    }
}

extern "C" void kernel_launch(void* const* d_in, const int* in_sizes, int n_in,
                              void* d_out, int out_size)
{
    const float4* in4 = (const float4*)d_in[0];   // voxel_features [V,4,4] f32
    const float4* W4  = (const float4*)d_in[1];   // W [32,4] f32
    const int*    vnp = (const int*)d_in[2];      // voxel_num_points [V] i32
    float4*       out = (float4*)d_out;           // [V,32] f32

    int V = in_sizes[2];
    int warps = (V + 31) / 32;
    int blocks = (warps * 32 + THREADS - 1) / THREADS;
    radar_sparse_kernel<<<blocks, THREADS>>>(in4, W4, vnp, out, V);
}